// round 16
// baseline (speedup 1.0000x reference)
#include <cuda_runtime.h>
#include <cuda_fp16.h>
#include <cstdint>
#include <math.h>

#define BSZ   8
#define NSEQ  4096
#define DM    1024
#define EPSC  1e-5f

// ---------------------------------------------------------------------------
// Scratch (device globals). fp16 stored as uint16_t.
// ---------------------------------------------------------------------------
#define XELEMS (8u * 4096u * 1024u)
__device__ uint16_t g_x16[XELEMS];                 // x fp16
__device__ uint16_t g_q16[XELEMS];                 // q fp16 (gated)
__device__ uint16_t g_k16[XELEMS];                 // k fp16
__device__ uint16_t g_v16[XELEMS];                 // v fp16
__device__ uint16_t g_w16[4u * 1048576u];          // 4 weights fp16
__device__ uint16_t g_kv16[8u * 1048576u];         // kv fp16
__device__ float    g_sk[8u * 1024u], g_sv[8u * 1024u];

// ---------------------------------------------------------------------------
// Helpers
// ---------------------------------------------------------------------------
__device__ __forceinline__ uint32_t smem_u32(const void* p) {
    uint32_t a;
    asm("{ .reg .u64 t; cvta.to.shared.u64 t, %1; cvt.u32.u64 %0, t; }" : "=r"(a) : "l"(p));
    return a;
}
__device__ __forceinline__ uint32_t packh2(float x, float y) {
    __half2 h = __floats2half2_rn(x, y);
    return *reinterpret_cast<uint32_t*>(&h);
}
__device__ __forceinline__ float2 unpackh2(uint32_t u) {
    __half2 h = *reinterpret_cast<__half2*>(&u);
    return __half22float2(h);
}
__device__ __forceinline__ void ldm_x4(uint32_t* d, uint32_t a) {
    asm volatile("ldmatrix.sync.aligned.m8n8.x4.shared.b16 {%0,%1,%2,%3}, [%4];"
                 : "=r"(d[0]), "=r"(d[1]), "=r"(d[2]), "=r"(d[3]) : "r"(a));
}
__device__ __forceinline__ void ldm_x4t(uint32_t* d, uint32_t a) {
    asm volatile("ldmatrix.sync.aligned.m8n8.x4.trans.shared.b16 {%0,%1,%2,%3}, [%4];"
                 : "=r"(d[0]), "=r"(d[1]), "=r"(d[2]), "=r"(d[3]) : "r"(a));
}
__device__ __forceinline__ void mma16816(float* d, const uint32_t* a, const uint32_t* b) {
    asm volatile("mma.sync.aligned.m16n8k16.row.col.f32.f16.f16.f32 "
                 "{%0,%1,%2,%3}, {%4,%5,%6,%7}, {%8,%9}, {%0,%1,%2,%3};"
                 : "+f"(d[0]), "+f"(d[1]), "+f"(d[2]), "+f"(d[3])
                 : "r"(a[0]), "r"(a[1]), "r"(a[2]), "r"(a[3]), "r"(b[0]), "r"(b[1]));
}
__device__ __forceinline__ void cpa16(uint32_t s, const void* g) {
    asm volatile("cp.async.cg.shared.global [%0], [%1], 16;" :: "r"(s), "l"(g));
}

// ===========================================================================
// Common config: BM=BN=128, BK=64, 128 threads, 4 warps, warp tile 64x64
// (single-B) / 64x(32+32) (dual-B). 3-stage cp.async, one sync per BK=64.
// A smem (direct): [128 m][64 k], 128B rows, chunk^(m&7) swizzle  (16 KB)
// A smem (TRA)   : [64 k][128 m], 256B rows, chunk^(k&7) swizzle  (16 KB)
// B smem         : [64 k][128 n], 256B rows, chunk^(k&7) swizzle  (16 KB)
// B_o smem (dual): [64 k][64 n],  128B rows, chunk^(k&7) swizzle  (8 KB x2)
// ===========================================================================
#define STG_BYTES 32768u
#define SMEM_BYTES 98304

// ---------------------------------------------------------------------------
// Fused dual-B GEMM (stage 1). EPI 0: C0 = fp16(relu(a)*relu(b)).
// EPI 1: C0 = fp16(a), C1 = fp16(b).
// ---------------------------------------------------------------------------
template <int EPI>
__global__ __launch_bounds__(128, 2)
void tgemm2(const uint16_t* __restrict__ Ap, const uint16_t* __restrict__ B0p,
            const uint16_t* __restrict__ B1p,
            uint32_t* __restrict__ C0, uint32_t* __restrict__ C1,
            int K, int lda, int ldb, int ldc)
{
    extern __shared__ char smem[];
    const uint32_t sb = smem_u32(smem);
    const int tid = threadIdx.x;
    const int wid = tid >> 5, lid = tid & 31;
    const int brow = blockIdx.y * 128;
    const int bcol = blockIdx.x * 64;

    const int m0 = (wid & 1) * 64;
    const int n0 = (wid >> 1) * 32;

    float acc[2][4][4][4];   // [out][mi][n8][4]
#pragma unroll
    for (int o = 0; o < 2; ++o)
#pragma unroll
        for (int a = 0; a < 4; ++a)
#pragma unroll
            for (int b = 0; b < 4; ++b)
#pragma unroll
                for (int d = 0; d < 4; ++d) acc[o][a][b][d] = 0.f;

    const int NC = K / 64;

    auto issue = [&](int c) {
        const uint32_t st = sb + (uint32_t)(c % 3) * STG_BYTES;
        const int koff = c * 64;
        // A: [128 m][64 k] fp16, 128B rows
#pragma unroll
        for (int i = 0; i < 8; ++i) {
            int idx = tid + i * 128;
            int m = idx >> 3, cc = idx & 7;
            int g = (brow + m) * lda + koff + cc * 8;
            uint32_t off = m * 128 + (((uint32_t)(cc ^ (m & 7))) << 4);
            cpa16(st + off, Ap + g);
        }
        // B0/B1: [64 k][64 n] fp16, 128B rows
#pragma unroll
        for (int i = 0; i < 4; ++i) {
            int idx = tid + i * 128;
            int kk = idx >> 3, cc = idx & 7;
            int g = (koff + kk) * ldb + bcol + cc * 8;
            uint32_t off = kk * 128 + (((uint32_t)(cc ^ (kk & 7))) << 4);
            cpa16(st + 16384 + off, B0p + g);
            cpa16(st + 24576 + off, B1p + g);
        }
        asm volatile("cp.async.commit_group;" ::: "memory");
    };

    auto compute = [&](int c) {
        const uint32_t st = sb + (uint32_t)(c % 3) * STG_BYTES;
#pragma unroll
        for (int ks = 0; ks < 4; ++ks) {
            uint32_t af[4][4];
#pragma unroll
            for (int mi = 0; mi < 4; ++mi) {
                int row = m0 + mi * 16 + (lid & 15);
                int ch = ks * 2 + (lid >> 4);
                uint32_t off = row * 128 + (((uint32_t)(ch ^ (row & 7))) << 4);
                ldm_x4(af[mi], st + off);
            }
#pragma unroll
            for (int o = 0; o < 2; ++o) {
#pragma unroll
                for (int ni = 0; ni < 2; ++ni) {
                    int krow = ks * 16 + (lid & 7) + (lid & 8);
                    int ch = ((n0 + ni * 16) >> 3) + (lid >> 4);
                    uint32_t off = krow * 128 + (((uint32_t)(ch ^ (krow & 7))) << 4)
                                 + 16384 + (uint32_t)o * 8192;
                    uint32_t t[4];
                    ldm_x4t(t, st + off);
#pragma unroll
                    for (int mi = 0; mi < 4; ++mi) {
                        mma16816(acc[o][mi][ni * 2],     af[mi], &t[0]);
                        mma16816(acc[o][mi][ni * 2 + 1], af[mi], &t[2]);
                    }
                }
            }
        }
    };

    issue(0);
    issue(1);
    for (int c = 0; c < NC; ++c) {
        if (c + 1 < NC) asm volatile("cp.async.wait_group 1;" ::: "memory");
        else            asm volatile("cp.async.wait_group 0;" ::: "memory");
        __syncthreads();
        if (c + 2 < NC) issue(c + 2);
        compute(c);
    }

    // ---- epilogue ----
    const int r0 = lid >> 2;
    const int c0 = (lid & 3) * 2;
#pragma unroll
    for (int mi = 0; mi < 4; ++mi) {
#pragma unroll
        for (int half = 0; half < 2; ++half) {
            const int row = brow + m0 + mi * 16 + r0 + half * 8;
#pragma unroll
            for (int n8 = 0; n8 < 4; ++n8) {
                const int col = bcol + n0 + n8 * 8 + c0;
                long long lidx = ((long long)row * ldc + col) >> 1;
                float a0 = acc[0][mi][n8][half * 2];
                float a1 = acc[0][mi][n8][half * 2 + 1];
                float b0 = acc[1][mi][n8][half * 2];
                float b1 = acc[1][mi][n8][half * 2 + 1];
                if (EPI == 0) {
                    float q0 = fmaxf(a0, 0.f) * fmaxf(b0, 0.f);
                    float q1 = fmaxf(a1, 0.f) * fmaxf(b1, 0.f);
                    C0[lidx] = packh2(q0, q1);
                } else {
                    C0[lidx] = packh2(a0, a1);
                    C1[lidx] = packh2(b0, b1);
                }
            }
        }
    }
}

// ---------------------------------------------------------------------------
// Single-B GEMM (stages 4, 5). MODE 0: fp32 C0. MODE 3: scale+relu -> fp16.
// ---------------------------------------------------------------------------
template <bool TRA, int MODE>
__global__ __launch_bounds__(128, 2)
void tgemm(const uint16_t* __restrict__ Ap, const uint16_t* __restrict__ Bp,
           void* __restrict__ C0,
           int K, int lda, int ldb, int ldc,
           long long sA, long long sB, long long sC,
           const float* __restrict__ aux1, const float* __restrict__ aux2)
{
    extern __shared__ char smem[];
    const uint32_t sb = smem_u32(smem);
    const int tid = threadIdx.x;
    const int wid = tid >> 5, lid = tid & 31;
    const int z = blockIdx.z;
    const int brow = blockIdx.y * 128;
    const int bcol = blockIdx.x * 128;
    const uint16_t* A_p = Ap + z * sA;
    const uint16_t* B_p = Bp + z * sB;

    const int m0 = (wid & 1) * 64;
    const int n0 = (wid >> 1) * 64;

    float acc[4][8][4];
#pragma unroll
    for (int a = 0; a < 4; ++a)
#pragma unroll
        for (int b = 0; b < 8; ++b)
#pragma unroll
            for (int d = 0; d < 4; ++d) acc[a][b][d] = 0.f;

    const int NC = K / 64;

    auto issue = [&](int c) {
        const uint32_t st = sb + (uint32_t)(c % 3) * STG_BYTES;
        const int koff = c * 64;
        if (TRA) {
            // A: [64 k][128 m], 256B rows
#pragma unroll
            for (int i = 0; i < 8; ++i) {
                int idx = tid + i * 128;
                int kk = idx >> 4, cc = idx & 15;
                int g = (koff + kk) * lda + brow + cc * 8;
                uint32_t off = kk * 256 + (((uint32_t)(cc ^ (kk & 7))) << 4);
                cpa16(st + off, A_p + g);
            }
        } else {
            // A: [128 m][64 k], 128B rows
#pragma unroll
            for (int i = 0; i < 8; ++i) {
                int idx = tid + i * 128;
                int m = idx >> 3, cc = idx & 7;
                int g = (brow + m) * lda + koff + cc * 8;
                uint32_t off = m * 128 + (((uint32_t)(cc ^ (m & 7))) << 4);
                cpa16(st + off, A_p + g);
            }
        }
        // B: [64 k][128 n], 256B rows
#pragma unroll
        for (int i = 0; i < 8; ++i) {
            int idx = tid + i * 128;
            int kk = idx >> 4, cc = idx & 15;
            int g = (koff + kk) * ldb + bcol + cc * 8;
            uint32_t off = kk * 256 + (((uint32_t)(cc ^ (kk & 7))) << 4);
            cpa16(st + 16384 + off, B_p + g);
        }
        asm volatile("cp.async.commit_group;" ::: "memory");
    };

    auto compute = [&](int c) {
        const uint32_t st = sb + (uint32_t)(c % 3) * STG_BYTES;
#pragma unroll
        for (int ks = 0; ks < 4; ++ks) {
            uint32_t af[4][4];
#pragma unroll
            for (int mi = 0; mi < 4; ++mi) {
                if (TRA) {
                    int krow = ks * 16 + (lid & 7) + ((lid & 16) >> 1);
                    int ch = ((m0 + mi * 16) >> 3) + ((lid >> 3) & 1);
                    uint32_t off = krow * 256 + (((uint32_t)(ch ^ (krow & 7))) << 4);
                    ldm_x4t(af[mi], st + off);
                } else {
                    int row = m0 + mi * 16 + (lid & 15);
                    int ch = ks * 2 + (lid >> 4);
                    uint32_t off = row * 128 + (((uint32_t)(ch ^ (row & 7))) << 4);
                    ldm_x4(af[mi], st + off);
                }
            }
#pragma unroll
            for (int ni = 0; ni < 4; ++ni) {
                int krow = ks * 16 + (lid & 7) + (lid & 8);
                int ch = ((n0 + ni * 16) >> 3) + (lid >> 4);
                uint32_t off = krow * 256 + (((uint32_t)(ch ^ (krow & 7))) << 4) + 16384;
                uint32_t t[4];
                ldm_x4t(t, st + off);
#pragma unroll
                for (int mi = 0; mi < 4; ++mi) {
                    mma16816(acc[mi][ni * 2],     af[mi], &t[0]);
                    mma16816(acc[mi][ni * 2 + 1], af[mi], &t[2]);
                }
            }
        }
    };

    issue(0);
    issue(1);
    for (int c = 0; c < NC; ++c) {
        if (c + 1 < NC) asm volatile("cp.async.wait_group 1;" ::: "memory");
        else            asm volatile("cp.async.wait_group 0;" ::: "memory");
        __syncthreads();
        if (c + 2 < NC) issue(c + 2);
        compute(c);
    }

    // ---- epilogue ----
    const int r0 = lid >> 2;
    const int c0 = (lid & 3) * 2;
#pragma unroll
    for (int mi = 0; mi < 4; ++mi) {
#pragma unroll
        for (int half = 0; half < 2; ++half) {
            const int row = brow + m0 + mi * 16 + r0 + half * 8;
            float s1 = 1.f;
            if (MODE == 3) s1 = aux1[z * DM + row];
#pragma unroll
            for (int n8 = 0; n8 < 8; ++n8) {
                float d0 = acc[mi][n8][half * 2];
                float d1 = acc[mi][n8][half * 2 + 1];
                const int col = bcol + n0 + n8 * 8 + c0;
                if (MODE == 3) {
                    d0 = fmaxf(d0 * s1 * aux2[z * DM + col], 0.f);
                    d1 = fmaxf(d1 * s1 * aux2[z * DM + col + 1], 0.f);
                }
                long long lidx = (long long)z * sC + (long long)row * ldc + col;
                if (MODE == 0) {
                    *(float2*)((float*)C0 + lidx) = make_float2(d0, d1);
                } else {
                    ((uint32_t*)C0)[lidx >> 1] = packh2(d0, d1);
                }
            }
        }
    }
}

// ---------------------------------------------------------------------------
// Elementwise kernels
// ---------------------------------------------------------------------------
__global__ void cvt_h(const float4* __restrict__ in, uint2* __restrict__ o, int n4)
{
    int i = blockIdx.x * blockDim.x + threadIdx.x;
    if (i < n4) {
        float4 v = in[i];
        o[i] = make_uint2(packh2(v.x, v.y), packh2(v.z, v.w));
    }
}

// dual-input inverse L2 norm over sequence axis from fp16
__global__ void col_scale2_h(const uint32_t* __restrict__ X0, const uint32_t* __restrict__ X1,
                             float* __restrict__ S0, float* __restrict__ S1)
{
    __shared__ float red0[256], red1[256];
    const uint32_t* X = blockIdx.z ? X1 : X0;
    float* S = blockIdx.z ? S1 : S0;
    const int lane = threadIdx.x & 31;
    const int sl = threadIdx.x >> 5;
    const int e2 = blockIdx.x * 32 + lane;
    const int b = blockIdx.y;
    const int base = b * (NSEQ * DM / 2) + e2;
    float s0 = 0.f, s1 = 0.f;
    for (int n = sl; n < NSEQ; n += 8) {
        float2 f = unpackh2(X[base + n * (DM / 2)]);
        s0 += f.x * f.x;
        s1 += f.y * f.y;
    }
    red0[threadIdx.x] = s0;
    red1[threadIdx.x] = s1;
    __syncthreads();
    if (sl == 0) {
        float t0 = 0.f, t1 = 0.f;
#pragma unroll
        for (int i = 0; i < 8; ++i) { t0 += red0[i * 32 + lane]; t1 += red1[i * 32 + lane]; }
        S[b * DM + e2 * 2]     = 1.f / (sqrtf(t0) + EPSC);
        S[b * DM + e2 * 2 + 1] = 1.f / (sqrtf(t1) + EPSC);
    }
}

// ---------------------------------------------------------------------------
// Launch
// ---------------------------------------------------------------------------
extern "C" void kernel_launch(void* const* d_in, const int* in_sizes, int n_in,
                              void* d_out, int out_size)
{
    const float* x   = (const float*)d_in[0];
    const float* wqr = (const float*)d_in[1];
    const float* wqi = (const float*)d_in[2];
    const float* wk  = (const float*)d_in[3];
    const float* wv  = (const float*)d_in[4];
    float* out = (float*)d_out;

    uint16_t *x16, *q16, *k16, *v16, *w16, *kv16;
    float *sk, *sv;
    cudaGetSymbolAddress((void**)&x16,  g_x16);
    cudaGetSymbolAddress((void**)&q16,  g_q16);
    cudaGetSymbolAddress((void**)&k16,  g_k16);
    cudaGetSymbolAddress((void**)&v16,  g_v16);
    cudaGetSymbolAddress((void**)&w16,  g_w16);
    cudaGetSymbolAddress((void**)&kv16, g_kv16);
    cudaGetSymbolAddress((void**)&sk,   g_sk);
    cudaGetSymbolAddress((void**)&sv,   g_sv);

    cudaFuncSetAttribute(tgemm2<0>,       cudaFuncAttributeMaxDynamicSharedMemorySize, SMEM_BYTES);
    cudaFuncSetAttribute(tgemm2<1>,       cudaFuncAttributeMaxDynamicSharedMemorySize, SMEM_BYTES);
    cudaFuncSetAttribute(tgemm<false, 0>, cudaFuncAttributeMaxDynamicSharedMemorySize, SMEM_BYTES);
    cudaFuncSetAttribute(tgemm<true, 3>,  cudaFuncAttributeMaxDynamicSharedMemorySize, SMEM_BYTES);

    // Input conversions to fp16
    cvt_h<<<XELEMS / 4 / 256, 256>>>((const float4*)x, (uint2*)x16, XELEMS / 4);
    const int wn4 = 1048576 / 4;
    cvt_h<<<wn4 / 256, 256>>>((const float4*)wqr, (uint2*)w16,             wn4);
    cvt_h<<<wn4 / 256, 256>>>((const float4*)wqi, (uint2*)(w16 + 1048576), wn4);
    cvt_h<<<wn4 / 256, 256>>>((const float4*)wk,  (uint2*)(w16 + 2097152), wn4);
    cvt_h<<<wn4 / 256, 256>>>((const float4*)wv,  (uint2*)(w16 + 3145728), wn4);

    // Stage 1 fused: q (gated) and k/v in two dual-B GEMMs
    dim3 gf(DM / 64, (BSZ * NSEQ) / 128, 1);
    tgemm2<0><<<gf, 128, SMEM_BYTES>>>(x16, w16,             w16 + 1048576,
                                       (uint32_t*)q16, nullptr, DM, DM, DM, DM);
    tgemm2<1><<<gf, 128, SMEM_BYTES>>>(x16, w16 + 2097152,   w16 + 3145728,
                                       (uint32_t*)k16, (uint32_t*)v16, DM, DM, DM, DM);

    // Stage 3: inverse L2 norms (k and v in one launch)
    dim3 gs(DM / 64, BSZ, 2);
    col_scale2_h<<<gs, 256>>>((const uint32_t*)k16, (const uint32_t*)v16, sk, sv);

    // Stage 4: kv[b] = relu((K^T V) .* sk x sv) -> fp16
    dim3 g2(DM / 128, DM / 128, BSZ);
    tgemm<true, 3><<<g2, 128, SMEM_BYTES>>>(k16, v16, kv16,
                                            NSEQ, DM, DM, DM,
                                            (long long)NSEQ * DM, (long long)NSEQ * DM,
                                            (long long)DM * DM, sk, sv);

    // Stage 5: out[b] = q[b] @ kv[b] -> fp32
    dim3 g3(DM / 128, NSEQ / 128, BSZ);
    tgemm<false, 0><<<g3, 128, SMEM_BYTES>>>(q16, kv16, out,
                                             DM, DM, DM, DM,
                                             (long long)NSEQ * DM, (long long)DM * DM,
                                             (long long)NSEQ * DM, nullptr, nullptr);
}

// round 17
// speedup vs baseline: 1.0023x; 1.0023x over previous
#include <cuda_runtime.h>
#include <cuda_fp16.h>
#include <cstdint>
#include <math.h>

#define BSZ   8
#define NSEQ  4096
#define DM    1024
#define EPSC  1e-5f

// ---------------------------------------------------------------------------
// Scratch (device globals). fp16 stored as uint16_t.
// ---------------------------------------------------------------------------
#define XELEMS (8u * 4096u * 1024u)
__device__ uint16_t g_x16[XELEMS];                 // x fp16
__device__ uint16_t g_q16[XELEMS];                 // q fp16 (gated)
__device__ uint16_t g_k16[XELEMS];                 // k fp16
__device__ uint16_t g_v16[XELEMS];                 // v fp16
__device__ uint16_t g_w16[4u * 1048576u];          // 4 weights fp16
__device__ uint16_t g_kv16[8u * 1048576u];         // kv fp16
__device__ float    g_sk[8u * 1024u], g_sv[8u * 1024u];

// ---------------------------------------------------------------------------
// Helpers
// ---------------------------------------------------------------------------
__device__ __forceinline__ uint32_t smem_u32(const void* p) {
    uint32_t a;
    asm("{ .reg .u64 t; cvta.to.shared.u64 t, %1; cvt.u32.u64 %0, t; }" : "=r"(a) : "l"(p));
    return a;
}
__device__ __forceinline__ uint32_t packh2(float x, float y) {
    __half2 h = __floats2half2_rn(x, y);
    return *reinterpret_cast<uint32_t*>(&h);
}
__device__ __forceinline__ float2 unpackh2(uint32_t u) {
    __half2 h = *reinterpret_cast<__half2*>(&u);
    return __half22float2(h);
}
__device__ __forceinline__ void ldm_x4(uint32_t* d, uint32_t a) {
    asm volatile("ldmatrix.sync.aligned.m8n8.x4.shared.b16 {%0,%1,%2,%3}, [%4];"
                 : "=r"(d[0]), "=r"(d[1]), "=r"(d[2]), "=r"(d[3]) : "r"(a));
}
__device__ __forceinline__ void ldm_x4t(uint32_t* d, uint32_t a) {
    asm volatile("ldmatrix.sync.aligned.m8n8.x4.trans.shared.b16 {%0,%1,%2,%3}, [%4];"
                 : "=r"(d[0]), "=r"(d[1]), "=r"(d[2]), "=r"(d[3]) : "r"(a));
}
__device__ __forceinline__ void mma16816(float* d, const uint32_t* a, const uint32_t* b) {
    asm volatile("mma.sync.aligned.m16n8k16.row.col.f32.f16.f16.f32 "
                 "{%0,%1,%2,%3}, {%4,%5,%6,%7}, {%8,%9}, {%0,%1,%2,%3};"
                 : "+f"(d[0]), "+f"(d[1]), "+f"(d[2]), "+f"(d[3])
                 : "r"(a[0]), "r"(a[1]), "r"(a[2]), "r"(a[3]), "r"(b[0]), "r"(b[1]));
}
__device__ __forceinline__ void cpa16(uint32_t s, const void* g) {
    asm volatile("cp.async.cg.shared.global [%0], [%1], 16;" :: "r"(s), "l"(g));
}

// ===========================================================================
// Common config: BM=BN=128, BK=64, 128 threads, 4 warps, warp tile 64x64
// (single-B) / 64x(32+32) (dual-B). 3-stage cp.async, one sync per BK=64.
// A smem (direct): [128 m][64 k], 128B rows, chunk^(m&7) swizzle  (16 KB)
// A smem (TRA)   : [64 k][128 m], 256B rows, chunk^(k&7) swizzle  (16 KB)
// B smem         : [64 k][128 n], 256B rows, chunk^(k&7) swizzle  (16 KB)
// B_o smem (dual): [64 k][64 n],  128B rows, chunk^(k&7) swizzle  (8 KB x2)
// ===========================================================================
#define STG_BYTES 32768u
#define SMEM_BYTES 98304

// ---------------------------------------------------------------------------
// Fused dual-B GEMM (stage 1). EPI 0: C0 = fp16(relu(a)*relu(b)).
// EPI 1: C0 = fp16(a), C1 = fp16(b).
// ---------------------------------------------------------------------------
template <int EPI>
__global__ __launch_bounds__(128, 2)
void tgemm2(const uint16_t* __restrict__ Ap, const uint16_t* __restrict__ B0p,
            const uint16_t* __restrict__ B1p,
            uint32_t* __restrict__ C0, uint32_t* __restrict__ C1,
            int K, int lda, int ldb, int ldc)
{
    extern __shared__ char smem[];
    const uint32_t sb = smem_u32(smem);
    const int tid = threadIdx.x;
    const int wid = tid >> 5, lid = tid & 31;
    const int brow = blockIdx.y * 128;
    const int bcol = blockIdx.x * 64;

    const int m0 = (wid & 1) * 64;
    const int n0 = (wid >> 1) * 32;

    float acc[2][4][4][4];   // [out][mi][n8][4]
#pragma unroll
    for (int o = 0; o < 2; ++o)
#pragma unroll
        for (int a = 0; a < 4; ++a)
#pragma unroll
            for (int b = 0; b < 4; ++b)
#pragma unroll
                for (int d = 0; d < 4; ++d) acc[o][a][b][d] = 0.f;

    const int NC = K / 64;

    auto issue = [&](int c) {
        const uint32_t st = sb + (uint32_t)(c % 3) * STG_BYTES;
        const int koff = c * 64;
        // A: [128 m][64 k] fp16, 128B rows
#pragma unroll
        for (int i = 0; i < 8; ++i) {
            int idx = tid + i * 128;
            int m = idx >> 3, cc = idx & 7;
            int g = (brow + m) * lda + koff + cc * 8;
            uint32_t off = m * 128 + (((uint32_t)(cc ^ (m & 7))) << 4);
            cpa16(st + off, Ap + g);
        }
        // B0/B1: [64 k][64 n] fp16, 128B rows
#pragma unroll
        for (int i = 0; i < 4; ++i) {
            int idx = tid + i * 128;
            int kk = idx >> 3, cc = idx & 7;
            int g = (koff + kk) * ldb + bcol + cc * 8;
            uint32_t off = kk * 128 + (((uint32_t)(cc ^ (kk & 7))) << 4);
            cpa16(st + 16384 + off, B0p + g);
            cpa16(st + 24576 + off, B1p + g);
        }
        asm volatile("cp.async.commit_group;" ::: "memory");
    };

    auto compute = [&](int c) {
        const uint32_t st = sb + (uint32_t)(c % 3) * STG_BYTES;
#pragma unroll
        for (int ks = 0; ks < 4; ++ks) {
            uint32_t af[4][4];
#pragma unroll
            for (int mi = 0; mi < 4; ++mi) {
                int row = m0 + mi * 16 + (lid & 15);
                int ch = ks * 2 + (lid >> 4);
                uint32_t off = row * 128 + (((uint32_t)(ch ^ (row & 7))) << 4);
                ldm_x4(af[mi], st + off);
            }
#pragma unroll
            for (int o = 0; o < 2; ++o) {
#pragma unroll
                for (int ni = 0; ni < 2; ++ni) {
                    int krow = ks * 16 + (lid & 7) + (lid & 8);
                    int ch = ((n0 + ni * 16) >> 3) + (lid >> 4);
                    uint32_t off = krow * 128 + (((uint32_t)(ch ^ (krow & 7))) << 4)
                                 + 16384 + (uint32_t)o * 8192;
                    uint32_t t[4];
                    ldm_x4t(t, st + off);
#pragma unroll
                    for (int mi = 0; mi < 4; ++mi) {
                        mma16816(acc[o][mi][ni * 2],     af[mi], &t[0]);
                        mma16816(acc[o][mi][ni * 2 + 1], af[mi], &t[2]);
                    }
                }
            }
        }
    };

    issue(0);
    issue(1);
    for (int c = 0; c < NC; ++c) {
        if (c + 1 < NC) asm volatile("cp.async.wait_group 1;" ::: "memory");
        else            asm volatile("cp.async.wait_group 0;" ::: "memory");
        __syncthreads();
        if (c + 2 < NC) issue(c + 2);
        compute(c);
    }

    // ---- epilogue ----
    const int r0 = lid >> 2;
    const int c0 = (lid & 3) * 2;
#pragma unroll
    for (int mi = 0; mi < 4; ++mi) {
#pragma unroll
        for (int half = 0; half < 2; ++half) {
            const int row = brow + m0 + mi * 16 + r0 + half * 8;
#pragma unroll
            for (int n8 = 0; n8 < 4; ++n8) {
                const int col = bcol + n0 + n8 * 8 + c0;
                long long lidx = ((long long)row * ldc + col) >> 1;
                float a0 = acc[0][mi][n8][half * 2];
                float a1 = acc[0][mi][n8][half * 2 + 1];
                float b0 = acc[1][mi][n8][half * 2];
                float b1 = acc[1][mi][n8][half * 2 + 1];
                if (EPI == 0) {
                    float q0 = fmaxf(a0, 0.f) * fmaxf(b0, 0.f);
                    float q1 = fmaxf(a1, 0.f) * fmaxf(b1, 0.f);
                    C0[lidx] = packh2(q0, q1);
                } else {
                    C0[lidx] = packh2(a0, a1);
                    C1[lidx] = packh2(b0, b1);
                }
            }
        }
    }
}

// ---------------------------------------------------------------------------
// Single-B GEMM (stages 4, 5). MODE 0: fp32 C0. MODE 3: scale+relu -> fp16.
// ---------------------------------------------------------------------------
template <bool TRA, int MODE>
__global__ __launch_bounds__(128, 2)
void tgemm(const uint16_t* __restrict__ Ap, const uint16_t* __restrict__ Bp,
           void* __restrict__ C0,
           int K, int lda, int ldb, int ldc,
           long long sA, long long sB, long long sC,
           const float* __restrict__ aux1, const float* __restrict__ aux2)
{
    extern __shared__ char smem[];
    const uint32_t sb = smem_u32(smem);
    const int tid = threadIdx.x;
    const int wid = tid >> 5, lid = tid & 31;
    const int z = blockIdx.z;
    const int brow = blockIdx.y * 128;
    const int bcol = blockIdx.x * 128;
    const uint16_t* A_p = Ap + z * sA;
    const uint16_t* B_p = Bp + z * sB;

    const int m0 = (wid & 1) * 64;
    const int n0 = (wid >> 1) * 64;

    float acc[4][8][4];
#pragma unroll
    for (int a = 0; a < 4; ++a)
#pragma unroll
        for (int b = 0; b < 8; ++b)
#pragma unroll
            for (int d = 0; d < 4; ++d) acc[a][b][d] = 0.f;

    const int NC = K / 64;

    auto issue = [&](int c) {
        const uint32_t st = sb + (uint32_t)(c % 3) * STG_BYTES;
        const int koff = c * 64;
        if (TRA) {
            // A: [64 k][128 m], 256B rows
#pragma unroll
            for (int i = 0; i < 8; ++i) {
                int idx = tid + i * 128;
                int kk = idx >> 4, cc = idx & 15;
                int g = (koff + kk) * lda + brow + cc * 8;
                uint32_t off = kk * 256 + (((uint32_t)(cc ^ (kk & 7))) << 4);
                cpa16(st + off, A_p + g);
            }
        } else {
            // A: [128 m][64 k], 128B rows
#pragma unroll
            for (int i = 0; i < 8; ++i) {
                int idx = tid + i * 128;
                int m = idx >> 3, cc = idx & 7;
                int g = (brow + m) * lda + koff + cc * 8;
                uint32_t off = m * 128 + (((uint32_t)(cc ^ (m & 7))) << 4);
                cpa16(st + off, A_p + g);
            }
        }
        // B: [64 k][128 n], 256B rows
#pragma unroll
        for (int i = 0; i < 8; ++i) {
            int idx = tid + i * 128;
            int kk = idx >> 4, cc = idx & 15;
            int g = (koff + kk) * ldb + bcol + cc * 8;
            uint32_t off = kk * 256 + (((uint32_t)(cc ^ (kk & 7))) << 4);
            cpa16(st + 16384 + off, B_p + g);
        }
        asm volatile("cp.async.commit_group;" ::: "memory");
    };

    auto compute = [&](int c) {
        const uint32_t st = sb + (uint32_t)(c % 3) * STG_BYTES;
#pragma unroll
        for (int ks = 0; ks < 4; ++ks) {
            uint32_t af[4][4];
#pragma unroll
            for (int mi = 0; mi < 4; ++mi) {
                if (TRA) {
                    int krow = ks * 16 + (lid & 7) + ((lid & 16) >> 1);
                    int ch = ((m0 + mi * 16) >> 3) + ((lid >> 3) & 1);
                    uint32_t off = krow * 256 + (((uint32_t)(ch ^ (krow & 7))) << 4);
                    ldm_x4t(af[mi], st + off);
                } else {
                    int row = m0 + mi * 16 + (lid & 15);
                    int ch = ks * 2 + (lid >> 4);
                    uint32_t off = row * 128 + (((uint32_t)(ch ^ (row & 7))) << 4);
                    ldm_x4(af[mi], st + off);
                }
            }
#pragma unroll
            for (int ni = 0; ni < 4; ++ni) {
                int krow = ks * 16 + (lid & 7) + (lid & 8);
                int ch = ((n0 + ni * 16) >> 3) + (lid >> 4);
                uint32_t off = krow * 256 + (((uint32_t)(ch ^ (krow & 7))) << 4) + 16384;
                uint32_t t[4];
                ldm_x4t(t, st + off);
#pragma unroll
                for (int mi = 0; mi < 4; ++mi) {
                    mma16816(acc[mi][ni * 2],     af[mi], &t[0]);
                    mma16816(acc[mi][ni * 2 + 1], af[mi], &t[2]);
                }
            }
        }
    };

    issue(0);
    issue(1);
    for (int c = 0; c < NC; ++c) {
        if (c + 1 < NC) asm volatile("cp.async.wait_group 1;" ::: "memory");
        else            asm volatile("cp.async.wait_group 0;" ::: "memory");
        __syncthreads();
        if (c + 2 < NC) issue(c + 2);
        compute(c);
    }

    // ---- epilogue ----
    const int r0 = lid >> 2;
    const int c0 = (lid & 3) * 2;
#pragma unroll
    for (int mi = 0; mi < 4; ++mi) {
#pragma unroll
        for (int half = 0; half < 2; ++half) {
            const int row = brow + m0 + mi * 16 + r0 + half * 8;
            float s1 = 1.f;
            if (MODE == 3) s1 = aux1[z * DM + row];
#pragma unroll
            for (int n8 = 0; n8 < 8; ++n8) {
                float d0 = acc[mi][n8][half * 2];
                float d1 = acc[mi][n8][half * 2 + 1];
                const int col = bcol + n0 + n8 * 8 + c0;
                if (MODE == 3) {
                    d0 = fmaxf(d0 * s1 * aux2[z * DM + col], 0.f);
                    d1 = fmaxf(d1 * s1 * aux2[z * DM + col + 1], 0.f);
                }
                long long lidx = (long long)z * sC + (long long)row * ldc + col;
                if (MODE == 0) {
                    *(float2*)((float*)C0 + lidx) = make_float2(d0, d1);
                } else {
                    ((uint32_t*)C0)[lidx >> 1] = packh2(d0, d1);
                }
            }
        }
    }
}

// ---------------------------------------------------------------------------
// Elementwise kernels
// ---------------------------------------------------------------------------
__global__ void cvt_h(const float4* __restrict__ in, uint2* __restrict__ o, int n4)
{
    int i = blockIdx.x * blockDim.x + threadIdx.x;
    if (i < n4) {
        float4 v = in[i];
        o[i] = make_uint2(packh2(v.x, v.y), packh2(v.z, v.w));
    }
}

// dual-input inverse L2 norm over sequence axis from fp16
__global__ void col_scale2_h(const uint32_t* __restrict__ X0, const uint32_t* __restrict__ X1,
                             float* __restrict__ S0, float* __restrict__ S1)
{
    __shared__ float red0[256], red1[256];
    const uint32_t* X = blockIdx.z ? X1 : X0;
    float* S = blockIdx.z ? S1 : S0;
    const int lane = threadIdx.x & 31;
    const int sl = threadIdx.x >> 5;
    const int e2 = blockIdx.x * 32 + lane;
    const int b = blockIdx.y;
    const int base = b * (NSEQ * DM / 2) + e2;
    float s0 = 0.f, s1 = 0.f;
    for (int n = sl; n < NSEQ; n += 8) {
        float2 f = unpackh2(X[base + n * (DM / 2)]);
        s0 += f.x * f.x;
        s1 += f.y * f.y;
    }
    red0[threadIdx.x] = s0;
    red1[threadIdx.x] = s1;
    __syncthreads();
    if (sl == 0) {
        float t0 = 0.f, t1 = 0.f;
#pragma unroll
        for (int i = 0; i < 8; ++i) { t0 += red0[i * 32 + lane]; t1 += red1[i * 32 + lane]; }
        S[b * DM + e2 * 2]     = 1.f / (sqrtf(t0) + EPSC);
        S[b * DM + e2 * 2 + 1] = 1.f / (sqrtf(t1) + EPSC);
    }
}

// ---------------------------------------------------------------------------
// Launch
// ---------------------------------------------------------------------------
extern "C" void kernel_launch(void* const* d_in, const int* in_sizes, int n_in,
                              void* d_out, int out_size)
{
    const float* x   = (const float*)d_in[0];
    const float* wqr = (const float*)d_in[1];
    const float* wqi = (const float*)d_in[2];
    const float* wk  = (const float*)d_in[3];
    const float* wv  = (const float*)d_in[4];
    float* out = (float*)d_out;

    uint16_t *x16, *q16, *k16, *v16, *w16, *kv16;
    float *sk, *sv;
    cudaGetSymbolAddress((void**)&x16,  g_x16);
    cudaGetSymbolAddress((void**)&q16,  g_q16);
    cudaGetSymbolAddress((void**)&k16,  g_k16);
    cudaGetSymbolAddress((void**)&v16,  g_v16);
    cudaGetSymbolAddress((void**)&w16,  g_w16);
    cudaGetSymbolAddress((void**)&kv16, g_kv16);
    cudaGetSymbolAddress((void**)&sk,   g_sk);
    cudaGetSymbolAddress((void**)&sv,   g_sv);

    cudaFuncSetAttribute(tgemm2<0>,       cudaFuncAttributeMaxDynamicSharedMemorySize, SMEM_BYTES);
    cudaFuncSetAttribute(tgemm2<1>,       cudaFuncAttributeMaxDynamicSharedMemorySize, SMEM_BYTES);
    cudaFuncSetAttribute(tgemm<false, 0>, cudaFuncAttributeMaxDynamicSharedMemorySize, SMEM_BYTES);
    cudaFuncSetAttribute(tgemm<true, 3>,  cudaFuncAttributeMaxDynamicSharedMemorySize, SMEM_BYTES);

    // Input conversions to fp16
    cvt_h<<<XELEMS / 4 / 256, 256>>>((const float4*)x, (uint2*)x16, XELEMS / 4);
    const int wn4 = 1048576 / 4;
    cvt_h<<<wn4 / 256, 256>>>((const float4*)wqr, (uint2*)w16,             wn4);
    cvt_h<<<wn4 / 256, 256>>>((const float4*)wqi, (uint2*)(w16 + 1048576), wn4);
    cvt_h<<<wn4 / 256, 256>>>((const float4*)wk,  (uint2*)(w16 + 2097152), wn4);
    cvt_h<<<wn4 / 256, 256>>>((const float4*)wv,  (uint2*)(w16 + 3145728), wn4);

    // Stage 1 fused: q (gated) and k/v in two dual-B GEMMs
    dim3 gf(DM / 64, (BSZ * NSEQ) / 128, 1);
    tgemm2<0><<<gf, 128, SMEM_BYTES>>>(x16, w16,             w16 + 1048576,
                                       (uint32_t*)q16, nullptr, DM, DM, DM, DM);
    tgemm2<1><<<gf, 128, SMEM_BYTES>>>(x16, w16 + 2097152,   w16 + 3145728,
                                       (uint32_t*)k16, (uint32_t*)v16, DM, DM, DM, DM);

    // Stage 3: inverse L2 norms (k and v in one launch)
    dim3 gs(DM / 64, BSZ, 2);
    col_scale2_h<<<gs, 256>>>((const uint32_t*)k16, (const uint32_t*)v16, sk, sv);

    // Stage 4: kv[b] = relu((K^T V) .* sk x sv) -> fp16
    dim3 g2(DM / 128, DM / 128, BSZ);
    tgemm<true, 3><<<g2, 128, SMEM_BYTES>>>(k16, v16, kv16,
                                            NSEQ, DM, DM, DM,
                                            (long long)NSEQ * DM, (long long)NSEQ * DM,
                                            (long long)DM * DM, sk, sv);

    // Stage 5: out[b] = q[b] @ kv[b] -> fp32
    dim3 g3(DM / 128, NSEQ / 128, BSZ);
    tgemm<false, 0><<<g3, 128, SMEM_BYTES>>>(q16, kv16, out,
                                             DM, DM, DM, DM,
                                             (long long)NSEQ * DM, (long long)DM * DM,
                                             (long long)NSEQ * DM, nullptr, nullptr);
}